// round 1
// baseline (speedup 1.0000x reference)
#include <cuda_runtime.h>

// Problem constants
#define BATCH   8
#define SEQ     1024
#define HEADS   12
#define DHEAD   64
#define DIN     768
#define DOUT    768
#define QKV_C   (3 * HEADS * DHEAD)     // 2304
#define MTOK    (BATCH * SEQ)           // 8192
#define HD      (HEADS * DHEAD)         // 768

// Scratch (static device memory — allocation-free per harness rules)
__device__ float g_qkv[(size_t)MTOK * QKV_C];                       // 75.5 MB
__device__ float g_scores[(size_t)BATCH * HEADS * SEQ * SEQ];       // 402.7 MB
__device__ float g_y[(size_t)MTOK * HD];                            // 25.2 MB

// ---------------------------------------------------------------------------
// Kernel: C[M,N] = A[M,K] @ B[K,N] + bias[N]
// 128x128 block tile, BK=16, 256 threads, 8x8 per-thread register tile.
// ---------------------------------------------------------------------------
__global__ __launch_bounds__(256) void sgemm_bias_kernel(
    const float* __restrict__ A, const float* __restrict__ Bm,
    const float* __restrict__ bias, float* __restrict__ C,
    int N, int K)
{
    const int BK = 16;
    __shared__ float As[BK][132];
    __shared__ float Bs[BK][132];

    int tid = threadIdx.x;
    int tx = tid & 15, ty = tid >> 4;
    const float* Ab = A + (size_t)blockIdx.y * 128 * K;
    const float* Bb = Bm + blockIdx.x * 128;

    float acc[8][8];
#pragma unroll
    for (int i = 0; i < 8; i++)
#pragma unroll
        for (int j = 0; j < 8; j++) acc[i][j] = 0.f;

    for (int k0 = 0; k0 < K; k0 += BK) {
#pragma unroll
        for (int i = 0; i < 2; i++) {
            int f = tid + 256 * i;
            int r = f >> 2, kc = (f & 3) << 2;
            float4 v = *(const float4*)(Ab + (size_t)r * K + k0 + kc);
            As[kc + 0][r] = v.x; As[kc + 1][r] = v.y;
            As[kc + 2][r] = v.z; As[kc + 3][r] = v.w;
        }
#pragma unroll
        for (int i = 0; i < 2; i++) {
            int f = tid + 256 * i;
            int r = f >> 5, nc = (f & 31) << 2;
            *(float4*)(&Bs[r][nc]) = *(const float4*)(Bb + (size_t)(k0 + r) * N + nc);
        }
        __syncthreads();
#pragma unroll
        for (int kk = 0; kk < BK; kk++) {
            float a[8], b[8];
#pragma unroll
            for (int i = 0; i < 8; i++) a[i] = As[kk][ty * 8 + i];
#pragma unroll
            for (int j = 0; j < 8; j++) b[j] = Bs[kk][tx * 8 + j];
#pragma unroll
            for (int i = 0; i < 8; i++)
#pragma unroll
                for (int j = 0; j < 8; j++) acc[i][j] += a[i] * b[j];
        }
        __syncthreads();
    }

    int row0 = blockIdx.y * 128 + ty * 8;
    int col0 = blockIdx.x * 128 + tx * 8;
    float4 bv0 = *(const float4*)(bias + col0);
    float4 bv1 = *(const float4*)(bias + col0 + 4);
#pragma unroll
    for (int i = 0; i < 8; i++) {
        float4 o0 = make_float4(acc[i][0] + bv0.x, acc[i][1] + bv0.y,
                                acc[i][2] + bv0.z, acc[i][3] + bv0.w);
        float4 o1 = make_float4(acc[i][4] + bv1.x, acc[i][5] + bv1.y,
                                acc[i][6] + bv1.z, acc[i][7] + bv1.w);
        *(float4*)(C + (size_t)(row0 + i) * N + col0) = o0;
        *(float4*)(C + (size_t)(row0 + i) * N + col0 + 4) = o1;
    }
}

// ---------------------------------------------------------------------------
// Kernel: scores[bh][i][j] = 0.125 * sum_d K[bh][i][d] * Q[bh][j][d]
// K rows i and Q rows j both live inside g_qkv with row stride QKV_C,
// d contiguous. Both operands transpose-loaded into [BK][row] smem tiles.
// Grid: (8 j-tiles, 8 i-tiles, 96 bh), 256 threads.
// ---------------------------------------------------------------------------
__global__ __launch_bounds__(256) void scores_kernel(
    const float* __restrict__ qkv, float* __restrict__ scores)
{
    const int BK = 16;
    __shared__ float As[BK][132];
    __shared__ float Bs[BK][132];

    int bh = blockIdx.z;
    int b = bh / HEADS, h = bh - b * HEADS;
    const float* head = qkv + (size_t)b * SEQ * QKV_C + h * DHEAD;
    const float* Ab = head + HD + (size_t)blockIdx.y * 128 * QKV_C;       // K rows (i)
    const float* Bb = head + (size_t)blockIdx.x * 128 * QKV_C;            // Q rows (j)
    float* Cb = scores + (size_t)bh * SEQ * SEQ
              + (size_t)blockIdx.y * 128 * SEQ + blockIdx.x * 128;

    int tid = threadIdx.x;
    int tx = tid & 15, ty = tid >> 4;

    float acc[8][8];
#pragma unroll
    for (int i = 0; i < 8; i++)
#pragma unroll
        for (int j = 0; j < 8; j++) acc[i][j] = 0.f;

    for (int k0 = 0; k0 < DHEAD; k0 += BK) {
#pragma unroll
        for (int i = 0; i < 2; i++) {
            int f = tid + 256 * i;
            int r = f >> 2, kc = (f & 3) << 2;
            float4 v = *(const float4*)(Ab + (size_t)r * QKV_C + k0 + kc);
            As[kc + 0][r] = v.x; As[kc + 1][r] = v.y;
            As[kc + 2][r] = v.z; As[kc + 3][r] = v.w;
            float4 w = *(const float4*)(Bb + (size_t)r * QKV_C + k0 + kc);
            Bs[kc + 0][r] = w.x; Bs[kc + 1][r] = w.y;
            Bs[kc + 2][r] = w.z; Bs[kc + 3][r] = w.w;
        }
        __syncthreads();
#pragma unroll
        for (int kk = 0; kk < BK; kk++) {
            float a[8], bb[8];
#pragma unroll
            for (int i = 0; i < 8; i++) a[i] = As[kk][ty * 8 + i];
#pragma unroll
            for (int j = 0; j < 8; j++) bb[j] = Bs[kk][tx * 8 + j];
#pragma unroll
            for (int i = 0; i < 8; i++)
#pragma unroll
                for (int j = 0; j < 8; j++) acc[i][j] += a[i] * bb[j];
        }
        __syncthreads();
    }

#pragma unroll
    for (int i = 0; i < 8; i++) {
        float4 o0 = make_float4(acc[i][0], acc[i][1], acc[i][2], acc[i][3]);
        float4 o1 = make_float4(acc[i][4], acc[i][5], acc[i][6], acc[i][7]);
        o0.x *= 0.125f; o0.y *= 0.125f; o0.z *= 0.125f; o0.w *= 0.125f;
        o1.x *= 0.125f; o1.y *= 0.125f; o1.z *= 0.125f; o1.w *= 0.125f;
        *(float4*)(Cb + (size_t)(ty * 8 + i) * SEQ + tx * 8) = o0;
        *(float4*)(Cb + (size_t)(ty * 8 + i) * SEQ + tx * 8 + 4) = o1;
    }
}

// ---------------------------------------------------------------------------
// Kernel: in-place row softmax over the last (j) axis. One warp per row,
// 32 floats per lane held in registers (single read + single write of HBM).
// Grid: (B*H*SEQ)/8 blocks of 256 threads.
// ---------------------------------------------------------------------------
__global__ __launch_bounds__(256) void softmax_kernel(float* __restrict__ scores)
{
    int warp = threadIdx.x >> 5, lane = threadIdx.x & 31;
    size_t row = (size_t)blockIdx.x * 8 + warp;
    float4* p = (float4*)(scores + row * SEQ);

    float4 v[8];
    float m = -3.4e38f;
#pragma unroll
    for (int i = 0; i < 8; i++) {
        v[i] = p[lane + 32 * i];
        m = fmaxf(m, fmaxf(fmaxf(v[i].x, v[i].y), fmaxf(v[i].z, v[i].w)));
    }
#pragma unroll
    for (int o = 16; o > 0; o >>= 1) m = fmaxf(m, __shfl_xor_sync(0xffffffffu, m, o));

    float s = 0.f;
#pragma unroll
    for (int i = 0; i < 8; i++) {
        v[i].x = __expf(v[i].x - m); v[i].y = __expf(v[i].y - m);
        v[i].z = __expf(v[i].z - m); v[i].w = __expf(v[i].w - m);
        s += v[i].x + v[i].y + v[i].z + v[i].w;
    }
#pragma unroll
    for (int o = 16; o > 0; o >>= 1) s += __shfl_xor_sync(0xffffffffu, s, o);
    float inv = 1.0f / s;

#pragma unroll
    for (int i = 0; i < 8; i++) {
        v[i].x *= inv; v[i].y *= inv; v[i].z *= inv; v[i].w *= inv;
        p[lane + 32 * i] = v[i];
    }
}

// ---------------------------------------------------------------------------
// Kernel: Y[bh][i][d] = sum_j P[bh][i][j] * V[bh][j][d]
// M=1024, N=64, K=1024 per bh. Block tile 128x64, 256 threads, 8x4 per thread.
// Grid: (8 i-tiles, 1, 96 bh).
// ---------------------------------------------------------------------------
__global__ __launch_bounds__(256) void av_kernel(
    const float* __restrict__ scores, const float* __restrict__ qkv,
    float* __restrict__ y)
{
    const int BK = 16;
    __shared__ float As[BK][132];   // P tile transposed: As[kk][i]
    __shared__ float Bs[BK][68];    // V tile: Bs[kk][d]

    int bh = blockIdx.z;
    int b = bh / HEADS, h = bh - b * HEADS;
    const float* Pb = scores + (size_t)bh * SEQ * SEQ + (size_t)blockIdx.x * 128 * SEQ;
    const float* Vb = qkv + (size_t)b * SEQ * QKV_C + 2 * HD + h * DHEAD;
    float* Cb = y + ((size_t)b * SEQ + blockIdx.x * 128) * HD + h * DHEAD;

    int tid = threadIdx.x;
    int tx = tid & 15, ty = tid >> 4;     // tx: 16 groups of 4 d; ty: 16 groups of 8 i

    float acc[8][4];
#pragma unroll
    for (int i = 0; i < 8; i++)
#pragma unroll
        for (int j = 0; j < 4; j++) acc[i][j] = 0.f;

    for (int k0 = 0; k0 < SEQ; k0 += BK) {
#pragma unroll
        for (int i = 0; i < 2; i++) {
            int f = tid + 256 * i;
            int r = f >> 2, kc = (f & 3) << 2;
            float4 v = *(const float4*)(Pb + (size_t)r * SEQ + k0 + kc);
            As[kc + 0][r] = v.x; As[kc + 1][r] = v.y;
            As[kc + 2][r] = v.z; As[kc + 3][r] = v.w;
        }
        {   // V tile: 16 j rows x 64 d, 256 float4, one per thread
            int r = tid >> 4, dc = (tid & 15) << 2;
            *(float4*)(&Bs[r][dc]) = *(const float4*)(Vb + (size_t)(k0 + r) * QKV_C + dc);
        }
        __syncthreads();
#pragma unroll
        for (int kk = 0; kk < BK; kk++) {
            float a[8], bb[4];
#pragma unroll
            for (int i = 0; i < 8; i++) a[i] = As[kk][ty * 8 + i];
#pragma unroll
            for (int j = 0; j < 4; j++) bb[j] = Bs[kk][tx * 4 + j];
#pragma unroll
            for (int i = 0; i < 8; i++)
#pragma unroll
                for (int j = 0; j < 4; j++) acc[i][j] += a[i] * bb[j];
        }
        __syncthreads();
    }

#pragma unroll
    for (int i = 0; i < 8; i++) {
        float4 o = make_float4(acc[i][0], acc[i][1], acc[i][2], acc[i][3]);
        *(float4*)(Cb + (size_t)(ty * 8 + i) * HD + tx * 4) = o;
    }
}

// ---------------------------------------------------------------------------
extern "C" void kernel_launch(void* const* d_in, const int* in_sizes, int n_in,
                              void* d_out, int out_size)
{
    (void)in_sizes; (void)n_in; (void)out_size;
    const float* x     = (const float*)d_in[0];
    const float* w_qkv = (const float*)d_in[1];
    const float* b_qkv = (const float*)d_in[2];
    const float* w_out = (const float*)d_in[3];
    const float* b_out = (const float*)d_in[4];
    float* out = (float*)d_out;

    float *qkv_p, *sc_p, *y_p;
    cudaGetSymbolAddress((void**)&qkv_p, g_qkv);
    cudaGetSymbolAddress((void**)&sc_p,  g_scores);
    cudaGetSymbolAddress((void**)&y_p,   g_y);

    // 1. QKV projection: [8192,768] @ [768,2304] + bias
    sgemm_bias_kernel<<<dim3(QKV_C / 128, MTOK / 128), 256>>>(
        x, w_qkv, b_qkv, qkv_p, QKV_C, DIN);

    // 2. scores = K @ Q^T / sqrt(64), per (b,h)
    scores_kernel<<<dim3(SEQ / 128, SEQ / 128, BATCH * HEADS), 256>>>(qkv_p, sc_p);

    // 3. row softmax over j
    softmax_kernel<<<(BATCH * HEADS * SEQ) / 8, 256>>>(sc_p);

    // 4. Y = P @ V, per (b,h)
    av_kernel<<<dim3(SEQ / 128, 1, BATCH * HEADS), 256>>>(sc_p, qkv_p, y_p);

    // 5. output projection: [8192,768] @ [768,768] + bias
    sgemm_bias_kernel<<<dim3(DOUT / 128, MTOK / 128), 256>>>(
        y_p, w_out, b_out, out, DOUT, HD);
}

// round 2
// speedup vs baseline: 1.7889x; 1.7889x over previous
#include <cuda_runtime.h>
#include <cstdint>

// Problem constants
#define BATCH   8
#define SEQ     1024
#define HEADS   12
#define DHEAD   64
#define DIN     768
#define DOUT    768
#define QKV_C   (3 * HEADS * DHEAD)     // 2304
#define MTOK    (BATCH * SEQ)           // 8192
#define HD      (HEADS * DHEAD)         // 768

// Scratch (static device memory — allocation-free per harness rules)
__device__ float g_qkv[(size_t)MTOK * QKV_C];                       // 75.5 MB
__device__ float g_scores[(size_t)BATCH * HEADS * SEQ * SEQ];       // 402.7 MB
__device__ float g_y[(size_t)MTOK * HD];                            // 25.2 MB

// ---------------------------------------------------------------------------
// tf32 helpers
// ---------------------------------------------------------------------------
__device__ __forceinline__ float f2tf32(float x) {
    unsigned u;
    asm("cvt.rna.tf32.f32 %0, %1;" : "=r"(u) : "f"(x));
    return __uint_as_float(u);
}

__device__ __forceinline__ void mma_tf32(float c[4],
                                         uint32_t a0, uint32_t a1, uint32_t a2, uint32_t a3,
                                         uint32_t b0, uint32_t b1)
{
    asm volatile(
        "mma.sync.aligned.m16n8k8.row.col.f32.tf32.tf32.f32 "
        "{%0,%1,%2,%3}, {%4,%5,%6,%7}, {%8,%9}, {%0,%1,%2,%3};\n"
        : "+f"(c[0]), "+f"(c[1]), "+f"(c[2]), "+f"(c[3])
        : "r"(a0), "r"(a1), "r"(a2), "r"(a3), "r"(b0), "r"(b1));
}

// ---------------------------------------------------------------------------
// Kernel: C[M,N] = A[M,K] @ B[K,N] + bias[N]   (tf32 tensor cores)
// 128x128 block, BK=16, 256 threads = 8 warps (2 in M x 4 in N),
// warp tile 64x32 = 4x4 grid of m16n8k8 mma tiles.
// Smem: As[k][m] (A transpose-loaded), Bs[k][n]. Both tf32-rounded at STS.
// ---------------------------------------------------------------------------
__global__ __launch_bounds__(256) void sgemm_bias_tc(
    const float* __restrict__ A, const float* __restrict__ Bm,
    const float* __restrict__ bias, float* __restrict__ C,
    int N, int K)
{
    const int BK = 16;
    __shared__ float As[BK][132];
    __shared__ float Bs[BK][132];

    int tid = threadIdx.x;
    int lane = tid & 31, warp = tid >> 5;
    int gid = lane >> 2, tig = lane & 3;
    int warp_m = warp & 1, warp_n = warp >> 1;

    const float* Ab = A + (size_t)blockIdx.y * 128 * K;
    const float* Bb = Bm + blockIdx.x * 128;

    float c[4][4][4];
#pragma unroll
    for (int mt = 0; mt < 4; mt++)
#pragma unroll
        for (int nt = 0; nt < 4; nt++)
#pragma unroll
            for (int r = 0; r < 4; r++) c[mt][nt][r] = 0.f;

    for (int k0 = 0; k0 < K; k0 += BK) {
#pragma unroll
        for (int i = 0; i < 2; i++) {
            int f = tid + 256 * i;
            int r = f >> 2, kc = (f & 3) << 2;
            float4 v = *(const float4*)(Ab + (size_t)r * K + k0 + kc);
            As[kc + 0][r] = f2tf32(v.x); As[kc + 1][r] = f2tf32(v.y);
            As[kc + 2][r] = f2tf32(v.z); As[kc + 3][r] = f2tf32(v.w);
        }
#pragma unroll
        for (int i = 0; i < 2; i++) {
            int f = tid + 256 * i;
            int r = f >> 5, nc = (f & 31) << 2;
            float4 v = *(const float4*)(Bb + (size_t)(k0 + r) * N + nc);
            Bs[r][nc + 0] = f2tf32(v.x); Bs[r][nc + 1] = f2tf32(v.y);
            Bs[r][nc + 2] = f2tf32(v.z); Bs[r][nc + 3] = f2tf32(v.w);
        }
        __syncthreads();

#pragma unroll
        for (int kk = 0; kk < BK; kk += 8) {
            uint32_t a[4][4], b[4][2];
#pragma unroll
            for (int mt = 0; mt < 4; mt++) {
                int m = warp_m * 64 + mt * 16 + gid;
                a[mt][0] = __float_as_uint(As[kk + tig][m]);
                a[mt][1] = __float_as_uint(As[kk + tig][m + 8]);
                a[mt][2] = __float_as_uint(As[kk + tig + 4][m]);
                a[mt][3] = __float_as_uint(As[kk + tig + 4][m + 8]);
            }
#pragma unroll
            for (int nt = 0; nt < 4; nt++) {
                int n = warp_n * 32 + nt * 8 + gid;
                b[nt][0] = __float_as_uint(Bs[kk + tig][n]);
                b[nt][1] = __float_as_uint(Bs[kk + tig + 4][n]);
            }
#pragma unroll
            for (int mt = 0; mt < 4; mt++)
#pragma unroll
                for (int nt = 0; nt < 4; nt++)
                    mma_tf32(c[mt][nt], a[mt][0], a[mt][1], a[mt][2], a[mt][3],
                             b[nt][0], b[nt][1]);
        }
        __syncthreads();
    }

    int row_base = blockIdx.y * 128 + warp_m * 64;
    int col_base = blockIdx.x * 128 + warp_n * 32;
#pragma unroll
    for (int nt = 0; nt < 4; nt++) {
        int col = col_base + nt * 8 + 2 * tig;
        float2 bv = *(const float2*)(bias + col);
#pragma unroll
        for (int mt = 0; mt < 4; mt++) {
            int row = row_base + mt * 16 + gid;
            float2 o0 = make_float2(c[mt][nt][0] + bv.x, c[mt][nt][1] + bv.y);
            float2 o1 = make_float2(c[mt][nt][2] + bv.x, c[mt][nt][3] + bv.y);
            *(float2*)(C + (size_t)row * N + col) = o0;
            *(float2*)(C + (size_t)(row + 8) * N + col) = o1;
        }
    }
}

// ---------------------------------------------------------------------------
// Kernel: scores[bh][i][j] = 0.125 * sum_d K[bh][i][d] * Q[bh][j][d]
// Both operands transpose-loaded into [k][row] smem tiles; tf32 mma inner.
// Grid: (8 j-tiles, 8 i-tiles, 96 bh), 256 threads.
// ---------------------------------------------------------------------------
__global__ __launch_bounds__(256) void scores_tc(
    const float* __restrict__ qkv, float* __restrict__ scores)
{
    const int BK = 16;
    __shared__ float As[BK][132];
    __shared__ float Bs[BK][132];

    int bh = blockIdx.z;
    int b = bh / HEADS, h = bh - b * HEADS;
    const float* head = qkv + (size_t)b * SEQ * QKV_C + h * DHEAD;
    const float* Ab = head + HD + (size_t)blockIdx.y * 128 * QKV_C;   // K rows (i)
    const float* Bb = head + (size_t)blockIdx.x * 128 * QKV_C;        // Q rows (j)
    float* Cb = scores + (size_t)bh * SEQ * SEQ
              + (size_t)blockIdx.y * 128 * SEQ + blockIdx.x * 128;

    int tid = threadIdx.x;
    int lane = tid & 31, warp = tid >> 5;
    int gid = lane >> 2, tig = lane & 3;
    int warp_m = warp & 1, warp_n = warp >> 1;

    float c[4][4][4];
#pragma unroll
    for (int mt = 0; mt < 4; mt++)
#pragma unroll
        for (int nt = 0; nt < 4; nt++)
#pragma unroll
            for (int r = 0; r < 4; r++) c[mt][nt][r] = 0.f;

    for (int k0 = 0; k0 < DHEAD; k0 += BK) {
#pragma unroll
        for (int i = 0; i < 2; i++) {
            int f = tid + 256 * i;
            int r = f >> 2, kc = (f & 3) << 2;
            float4 v = *(const float4*)(Ab + (size_t)r * QKV_C + k0 + kc);
            As[kc + 0][r] = f2tf32(v.x); As[kc + 1][r] = f2tf32(v.y);
            As[kc + 2][r] = f2tf32(v.z); As[kc + 3][r] = f2tf32(v.w);
            float4 w = *(const float4*)(Bb + (size_t)r * QKV_C + k0 + kc);
            Bs[kc + 0][r] = f2tf32(w.x); Bs[kc + 1][r] = f2tf32(w.y);
            Bs[kc + 2][r] = f2tf32(w.z); Bs[kc + 3][r] = f2tf32(w.w);
        }
        __syncthreads();

#pragma unroll
        for (int kk = 0; kk < BK; kk += 8) {
            uint32_t a[4][4], b2[4][2];
#pragma unroll
            for (int mt = 0; mt < 4; mt++) {
                int m = warp_m * 64 + mt * 16 + gid;
                a[mt][0] = __float_as_uint(As[kk + tig][m]);
                a[mt][1] = __float_as_uint(As[kk + tig][m + 8]);
                a[mt][2] = __float_as_uint(As[kk + tig + 4][m]);
                a[mt][3] = __float_as_uint(As[kk + tig + 4][m + 8]);
            }
#pragma unroll
            for (int nt = 0; nt < 4; nt++) {
                int n = warp_n * 32 + nt * 8 + gid;
                b2[nt][0] = __float_as_uint(Bs[kk + tig][n]);
                b2[nt][1] = __float_as_uint(Bs[kk + tig + 4][n]);
            }
#pragma unroll
            for (int mt = 0; mt < 4; mt++)
#pragma unroll
                for (int nt = 0; nt < 4; nt++)
                    mma_tf32(c[mt][nt], a[mt][0], a[mt][1], a[mt][2], a[mt][3],
                             b2[nt][0], b2[nt][1]);
        }
        __syncthreads();
    }

#pragma unroll
    for (int nt = 0; nt < 4; nt++) {
        int col = warp_n * 32 + nt * 8 + 2 * tig;
#pragma unroll
        for (int mt = 0; mt < 4; mt++) {
            int row = warp_m * 64 + mt * 16 + gid;
            float2 o0 = make_float2(c[mt][nt][0] * 0.125f, c[mt][nt][1] * 0.125f);
            float2 o1 = make_float2(c[mt][nt][2] * 0.125f, c[mt][nt][3] * 0.125f);
            *(float2*)(Cb + (size_t)row * SEQ + col) = o0;
            *(float2*)(Cb + (size_t)(row + 8) * SEQ + col) = o1;
        }
    }
}

// ---------------------------------------------------------------------------
// Kernel: in-place row softmax over the last (j) axis. One warp per row.
// ---------------------------------------------------------------------------
__global__ __launch_bounds__(256) void softmax_kernel(float* __restrict__ scores)
{
    int warp = threadIdx.x >> 5, lane = threadIdx.x & 31;
    size_t row = (size_t)blockIdx.x * 8 + warp;
    float4* p = (float4*)(scores + row * SEQ);

    float4 v[8];
    float m = -3.4e38f;
#pragma unroll
    for (int i = 0; i < 8; i++) {
        v[i] = p[lane + 32 * i];
        m = fmaxf(m, fmaxf(fmaxf(v[i].x, v[i].y), fmaxf(v[i].z, v[i].w)));
    }
#pragma unroll
    for (int o = 16; o > 0; o >>= 1) m = fmaxf(m, __shfl_xor_sync(0xffffffffu, m, o));

    float s = 0.f;
#pragma unroll
    for (int i = 0; i < 8; i++) {
        v[i].x = __expf(v[i].x - m); v[i].y = __expf(v[i].y - m);
        v[i].z = __expf(v[i].z - m); v[i].w = __expf(v[i].w - m);
        s += v[i].x + v[i].y + v[i].z + v[i].w;
    }
#pragma unroll
    for (int o = 16; o > 0; o >>= 1) s += __shfl_xor_sync(0xffffffffu, s, o);
    float inv = 1.0f / s;

#pragma unroll
    for (int i = 0; i < 8; i++) {
        v[i].x *= inv; v[i].y *= inv; v[i].z *= inv; v[i].w *= inv;
        p[lane + 32 * i] = v[i];
    }
}

// ---------------------------------------------------------------------------
// Kernel: Y[bh][i][d] = sum_j P[bh][i][j] * V[bh][j][d]   (tf32 tensor cores)
// Block 128x64, BK=16, 8 warps (4 in M x 2 in N), warp tile 32x32 =
// 2x4 grid of m16n8k8 tiles. Grid: (8 i-tiles, 1, 96 bh).
// ---------------------------------------------------------------------------
__global__ __launch_bounds__(256) void av_tc(
    const float* __restrict__ scores, const float* __restrict__ qkv,
    float* __restrict__ y)
{
    const int BK = 16;
    __shared__ float As[BK][132];   // P transposed: As[k][i]
    __shared__ float Bs[BK][68];    // V: Bs[k][d]

    int bh = blockIdx.z;
    int b = bh / HEADS, h = bh - b * HEADS;
    const float* Pb = scores + (size_t)bh * SEQ * SEQ + (size_t)blockIdx.x * 128 * SEQ;
    const float* Vb = qkv + (size_t)b * SEQ * QKV_C + 2 * HD + h * DHEAD;
    float* Cb = y + ((size_t)b * SEQ + blockIdx.x * 128) * HD + h * DHEAD;

    int tid = threadIdx.x;
    int lane = tid & 31, warp = tid >> 5;
    int gid = lane >> 2, tig = lane & 3;
    int warp_m = warp & 3, warp_n = warp >> 2;

    float c[2][4][4];
#pragma unroll
    for (int mt = 0; mt < 2; mt++)
#pragma unroll
        for (int nt = 0; nt < 4; nt++)
#pragma unroll
            for (int r = 0; r < 4; r++) c[mt][nt][r] = 0.f;

    for (int k0 = 0; k0 < SEQ; k0 += BK) {
#pragma unroll
        for (int i = 0; i < 2; i++) {
            int f = tid + 256 * i;
            int r = f >> 2, kc = (f & 3) << 2;
            float4 v = *(const float4*)(Pb + (size_t)r * SEQ + k0 + kc);
            As[kc + 0][r] = f2tf32(v.x); As[kc + 1][r] = f2tf32(v.y);
            As[kc + 2][r] = f2tf32(v.z); As[kc + 3][r] = f2tf32(v.w);
        }
        {   // V tile: 16 j rows x 64 d, 256 float4, one per thread
            int r = tid >> 4, dc = (tid & 15) << 2;
            float4 v = *(const float4*)(Vb + (size_t)(k0 + r) * QKV_C + dc);
            Bs[r][dc + 0] = f2tf32(v.x); Bs[r][dc + 1] = f2tf32(v.y);
            Bs[r][dc + 2] = f2tf32(v.z); Bs[r][dc + 3] = f2tf32(v.w);
        }
        __syncthreads();

#pragma unroll
        for (int kk = 0; kk < BK; kk += 8) {
            uint32_t a[2][4], b2[4][2];
#pragma unroll
            for (int mt = 0; mt < 2; mt++) {
                int m = warp_m * 32 + mt * 16 + gid;
                a[mt][0] = __float_as_uint(As[kk + tig][m]);
                a[mt][1] = __float_as_uint(As[kk + tig][m + 8]);
                a[mt][2] = __float_as_uint(As[kk + tig + 4][m]);
                a[mt][3] = __float_as_uint(As[kk + tig + 4][m + 8]);
            }
#pragma unroll
            for (int nt = 0; nt < 4; nt++) {
                int n = warp_n * 32 + nt * 8 + gid;
                b2[nt][0] = __float_as_uint(Bs[kk + tig][n]);
                b2[nt][1] = __float_as_uint(Bs[kk + tig + 4][n]);
            }
#pragma unroll
            for (int mt = 0; mt < 2; mt++)
#pragma unroll
                for (int nt = 0; nt < 4; nt++)
                    mma_tf32(c[mt][nt], a[mt][0], a[mt][1], a[mt][2], a[mt][3],
                             b2[nt][0], b2[nt][1]);
        }
        __syncthreads();
    }

#pragma unroll
    for (int nt = 0; nt < 4; nt++) {
        int col = warp_n * 32 + nt * 8 + 2 * tig;
#pragma unroll
        for (int mt = 0; mt < 2; mt++) {
            int row = warp_m * 32 + mt * 16 + gid;
            *(float2*)(Cb + (size_t)row * HD + col) =
                make_float2(c[mt][nt][0], c[mt][nt][1]);
            *(float2*)(Cb + (size_t)(row + 8) * HD + col) =
                make_float2(c[mt][nt][2], c[mt][nt][3]);
        }
    }
}

// ---------------------------------------------------------------------------
extern "C" void kernel_launch(void* const* d_in, const int* in_sizes, int n_in,
                              void* d_out, int out_size)
{
    (void)in_sizes; (void)n_in; (void)out_size;
    const float* x     = (const float*)d_in[0];
    const float* w_qkv = (const float*)d_in[1];
    const float* b_qkv = (const float*)d_in[2];
    const float* w_out = (const float*)d_in[3];
    const float* b_out = (const float*)d_in[4];
    float* out = (float*)d_out;

    float *qkv_p, *sc_p, *y_p;
    cudaGetSymbolAddress((void**)&qkv_p, g_qkv);
    cudaGetSymbolAddress((void**)&sc_p,  g_scores);
    cudaGetSymbolAddress((void**)&y_p,   g_y);

    // 1. QKV projection: [8192,768] @ [768,2304] + bias
    sgemm_bias_tc<<<dim3(QKV_C / 128, MTOK / 128), 256>>>(
        x, w_qkv, b_qkv, qkv_p, QKV_C, DIN);

    // 2. scores = K @ Q^T / sqrt(64), per (b,h)
    scores_tc<<<dim3(SEQ / 128, SEQ / 128, BATCH * HEADS), 256>>>(qkv_p, sc_p);

    // 3. row softmax over j
    softmax_kernel<<<(BATCH * HEADS * SEQ) / 8, 256>>>(sc_p);

    // 4. Y = P @ V, per (b,h)
    av_tc<<<dim3(SEQ / 128, 1, BATCH * HEADS), 256>>>(sc_p, qkv_p, y_p);

    // 5. output projection: [8192,768] @ [768,768] + bias
    sgemm_bias_tc<<<dim3(DOUT / 128, MTOK / 128), 256>>>(
        y_p, w_out, b_out, out, DOUT, HD);
}